// round 13
// baseline (speedup 1.0000x reference)
#include <cuda_runtime.h>
#include <cstdint>
#include <cstdio>

#define BQ 8
#define LQ 4096
#define DM 512
#define DI 1024
#define NS 16
#define DTR 32
#define CHUNK 256
#define NCHUNK (LQ / CHUNK) /* 16 */

typedef unsigned long long ull;

// ------------------------- scratch (device globals; no allocs) -------------
__device__ float g_W[DI * DM];
__device__ float g_c[DI];
__device__ float g_xa[(size_t)BQ * LQ * DI];
__device__ float g_xc[(size_t)BQ * LQ * DI];
__device__ float g_xdb[(size_t)BQ * LQ * 64];
__device__ float g_hpart[BQ * NCHUNK * NS * DI];
__device__ float g_sumdt[BQ * NCHUNK * DI];
__device__ float g_hfin[BQ * NS * DI];
__device__ float g_xplast[BQ * DM];
__device__ float g_zf[BQ * DI];
__device__ float g_zb[BQ * DI];
__device__ float g_xab0[BQ * DI];
__device__ float g_xcb0[BQ * DI];
__device__ float g_xdbb[BQ * 64];
__device__ float g_gf[BQ * DI];
__device__ float g_gb[BQ * DI];
__device__ float g_outf[BQ * DM];
__device__ float g_outb[BQ * DM];

__device__ __forceinline__ float silu_f(float x) {
    return x / (1.0f + __expf(-x));
}

// packed fp32x2 ops (Blackwell FMA pipe, exact fp32 math)
#define FMA_F32X2(d, a, b, c) \
    asm("fma.rn.f32x2 %0, %1, %2, %3;" : "=l"(d) : "l"(a), "l"(b), "l"(c))
#define ADD_F32X2(d, a, b) \
    asm("add.rn.f32x2 %0, %1, %2;" : "=l"(d) : "l"(a), "l"(b))
__device__ __forceinline__ ull pack_dup(float a) {
    ull r;
    uint32_t au = __float_as_uint(a);
    asm("mov.b64 %0, {%1, %1};" : "=l"(r) : "r"(au));
    return r;
}

// ------------------------- weight fold: W = in_wA (1024x512) @ proj_w (512x512)
__global__ void fold_kernel(const float* __restrict__ inwA,
                            const float* __restrict__ projw,
                            float* __restrict__ W) {
    __shared__ float As[16][16];
    __shared__ float Bs[16][17];
    int tx = threadIdx.x, ty = threadIdx.y;
    int m = blockIdx.y * 16 + ty;
    int n = blockIdx.x * 16 + tx;
    float acc = 0.f;
    for (int k0 = 0; k0 < DM; k0 += 16) {
        As[ty][tx] = inwA[(size_t)m * DM + k0 + tx];
        Bs[ty][tx] = projw[(size_t)(k0 + ty) * DM + n];
        __syncthreads();
#pragma unroll
        for (int k = 0; k < 16; k++) acc += As[ty][k] * Bs[k][tx];
        __syncthreads();
    }
    W[(size_t)m * DM + n] = acc;
}

__global__ void foldc_kernel(const float* __restrict__ inwA,
                             const float* __restrict__ projb,
                             float* __restrict__ c) {
    int m = blockIdx.x * blockDim.x + threadIdx.x;
    if (m >= DI) return;
    float s = 0.f;
    for (int k = 0; k < DM; k++) s += inwA[(size_t)m * DM + k] * projb[k];
    c[m] = s;
}

// ------------------------- big fp32 GEMM (f32x2 packed FMA) -----------------
// C[m,n] = sum_k A[m,k]*Bw[n,k] + bias[n]
// M=32768, N=1024, K=512.  128x128 tiles, BK=8, 256 thr, 8x8 microtile.
// Double-buffered smem; inner product uses fma.rn.f32x2 (2 cols per instr).
__global__ __launch_bounds__(256) void sgemm128_nt(
    const float* __restrict__ A, const float* __restrict__ Bw,
    const float* __restrict__ bias, float* __restrict__ C,
    int M, int N, int K) {
    __shared__ float As[2][8][128];
    __shared__ float Bs[2][8][128];
    const int tid = threadIdx.x;
    const int bm = blockIdx.y * 128, bn = blockIdx.x * 128;
    const int lr = tid >> 1, lk = (tid & 1) * 4;
    const int tx = tid & 15, ty = tid >> 4;
    const float* Ap = A + (size_t)(bm + lr) * K + lk;
    const float* Bp = Bw + (size_t)(bn + lr) * K + lk;
    ull acc2[8][4];
#pragma unroll
    for (int i = 0; i < 8; i++)
#pragma unroll
        for (int j = 0; j < 4; j++) acc2[i][j] = 0ull;

    float4 av = *(const float4*)(Ap);
    float4 bv = *(const float4*)(Bp);
    int cur = 0;
    for (int k0 = 0; k0 < K; k0 += 8) {
        As[cur][lk + 0][lr] = av.x; As[cur][lk + 1][lr] = av.y;
        As[cur][lk + 2][lr] = av.z; As[cur][lk + 3][lr] = av.w;
        Bs[cur][lk + 0][lr] = bv.x; Bs[cur][lk + 1][lr] = bv.y;
        Bs[cur][lk + 2][lr] = bv.z; Bs[cur][lk + 3][lr] = bv.w;
        if (k0 + 8 < K) {
            av = *(const float4*)(Ap + k0 + 8);
            bv = *(const float4*)(Bp + k0 + 8);
        }
        __syncthreads();
#pragma unroll
        for (int kk = 0; kk < 8; kk++) {
            float4 a0 = *(const float4*)&As[cur][kk][ty * 8];
            float4 a1 = *(const float4*)&As[cur][kk][ty * 8 + 4];
            const ull* bp2 = (const ull*)&Bs[cur][kk][tx * 8];
            ull b0 = bp2[0], b1 = bp2[1], b2 = bp2[2], b3 = bp2[3];
            float ar[8] = {a0.x, a0.y, a0.z, a0.w, a1.x, a1.y, a1.z, a1.w};
#pragma unroll
            for (int i = 0; i < 8; i++) {
                ull aa = pack_dup(ar[i]);
                FMA_F32X2(acc2[i][0], aa, b0, acc2[i][0]);
                FMA_F32X2(acc2[i][1], aa, b1, acc2[i][1]);
                FMA_F32X2(acc2[i][2], aa, b2, acc2[i][2]);
                FMA_F32X2(acc2[i][3], aa, b3, acc2[i][3]);
            }
        }
        cur ^= 1;
    }
    const ull* bias2 = (const ull*)&bias[bn + tx * 8];
    ull bb[4] = {bias2[0], bias2[1], bias2[2], bias2[3]};
#pragma unroll
    for (int i = 0; i < 8; i++) {
        float* crow = C + (size_t)(bm + ty * 8 + i) * N + bn + tx * 8;
#pragma unroll
        for (int j = 0; j < 4; j++) {
            ull o;
            ADD_F32X2(o, acc2[i][j], bb[j]);
            *(ull*)(crow + j * 2) = o;
        }
    }
}

// ------------------------- causal depthwise conv (4 taps) + silu
__global__ void conv_silu_kernel(const float* __restrict__ xa,
                                 const float* __restrict__ convw,
                                 const float* __restrict__ convb,
                                 float* __restrict__ xc) {
    size_t i = (size_t)blockIdx.x * blockDim.x + threadIdx.x;
    int d4 = (int)(i & 255);
    size_t bt = i >> 8;
    int t = (int)(bt & (LQ - 1));
    const float4* xa4 = (const float4*)xa;
    const float4* w4 = (const float4*)convw;
    float4 w0 = w4[d4 * 4 + 0], w1 = w4[d4 * 4 + 1];
    float4 w2 = w4[d4 * 4 + 2], w3 = w4[d4 * 4 + 3];
    float4 bias = ((const float4*)convb)[d4];
    float4 z4 = make_float4(0.f, 0.f, 0.f, 0.f);
    float4 xv3 = xa4[bt * 256 + d4];
    float4 xv2 = (t >= 1) ? xa4[(bt - 1) * 256 + d4] : z4;
    float4 xv1 = (t >= 2) ? xa4[(bt - 2) * 256 + d4] : z4;
    float4 xv0 = (t >= 3) ? xa4[(bt - 3) * 256 + d4] : z4;
    float o0 = w0.x * xv0.x + w0.y * xv1.x + w0.z * xv2.x + w0.w * xv3.x + bias.x;
    float o1 = w1.x * xv0.y + w1.y * xv1.y + w1.z * xv2.y + w1.w * xv3.y + bias.y;
    float o2 = w2.x * xv0.z + w2.y * xv1.z + w2.z * xv2.z + w2.w * xv3.z + bias.z;
    float o3 = w3.x * xv0.w + w3.y * xv1.w + w3.z * xv2.w + w3.w * xv3.w + bias.w;
    float4 out = make_float4(silu_f(o0), silu_f(o1), silu_f(o2), silu_f(o3));
    ((float4*)xc)[bt * 256 + d4] = out;
}

// ------------------------- xproj GEMM (f32x2): C[m,j<64] ---------------------
// M=32768, K=1024.  128x64 tiles, BK=8, 256 thr, 4x8 microtile.
__global__ __launch_bounds__(256) void sgemm_n64(
    const float* __restrict__ A, const float* __restrict__ Bw,
    float* __restrict__ C, int M, int K) {
    __shared__ float As[2][8][128];
    __shared__ float Bs[2][8][64];
    const int tid = threadIdx.x;
    const int bm = blockIdx.x * 128;
    const int lr = tid >> 1, lk = (tid & 1) * 4;
    const int tx = tid & 7, ty = tid >> 3;
    const int rb = tid >> 1, kb = (tid & 1) * 4;
    const float* Ap = A + (size_t)(bm + lr) * K + lk;
    ull acc2[4][4];
#pragma unroll
    for (int i = 0; i < 4; i++)
#pragma unroll
        for (int j = 0; j < 4; j++) acc2[i][j] = 0ull;

    float4 av = *(const float4*)(Ap);
    float4 bv = make_float4(0.f, 0.f, 0.f, 0.f);
    if (tid < 128) bv = *(const float4*)(Bw + (size_t)rb * K + kb);
    int cur = 0;
    for (int k0 = 0; k0 < K; k0 += 8) {
        As[cur][lk + 0][lr] = av.x; As[cur][lk + 1][lr] = av.y;
        As[cur][lk + 2][lr] = av.z; As[cur][lk + 3][lr] = av.w;
        if (tid < 128) {
            Bs[cur][kb + 0][rb] = bv.x; Bs[cur][kb + 1][rb] = bv.y;
            Bs[cur][kb + 2][rb] = bv.z; Bs[cur][kb + 3][rb] = bv.w;
        }
        if (k0 + 8 < K) {
            av = *(const float4*)(Ap + k0 + 8);
            if (tid < 128)
                bv = *(const float4*)(Bw + (size_t)rb * K + kb + k0 + 8);
        }
        __syncthreads();
#pragma unroll
        for (int kk = 0; kk < 8; kk++) {
            float4 a = *(const float4*)&As[cur][kk][ty * 4];
            const ull* bp2 = (const ull*)&Bs[cur][kk][tx * 8];
            ull b0 = bp2[0], b1 = bp2[1], b2 = bp2[2], b3 = bp2[3];
            float ar[4] = {a.x, a.y, a.z, a.w};
#pragma unroll
            for (int i = 0; i < 4; i++) {
                ull aa = pack_dup(ar[i]);
                FMA_F32X2(acc2[i][0], aa, b0, acc2[i][0]);
                FMA_F32X2(acc2[i][1], aa, b1, acc2[i][1]);
                FMA_F32X2(acc2[i][2], aa, b2, acc2[i][2]);
                FMA_F32X2(acc2[i][3], aa, b3, acc2[i][3]);
            }
        }
        cur ^= 1;
    }
#pragma unroll
    for (int i = 0; i < 4; i++) {
        float* crow = C + (size_t)(bm + ty * 4 + i) * 64 + tx * 8;
#pragma unroll
        for (int j = 0; j < 4; j++) *(ull*)(crow + j * 2) = acc2[i][j];
    }
}

// ------------------------- chunked selective scan, phase 1 ------------------
__global__ __launch_bounds__(128) void scan_chunk_kernel(
    const float* __restrict__ xc, const float* __restrict__ xdb,
    const float* __restrict__ dtw, const float* __restrict__ dtb,
    const float* __restrict__ Alog,
    float* __restrict__ hpart, float* __restrict__ sumdt) {
    const int d = blockIdx.x * 128 + threadIdx.x;
    const int c = blockIdx.y, b = blockIdx.z;
    float w[DTR];
#pragma unroll
    for (int r = 0; r < DTR; r++) w[r] = dtw[(size_t)d * DTR + r];
    const float bias = dtb[d];
    float a[NS];
    bool fast = true;
#pragma unroll
    for (int n = 0; n < NS; n++) {
        a[n] = -__expf(Alog[(size_t)d * NS + n]);
        fast = fast && (fabsf(a[n] + (float)(n + 1)) < 1e-4f * (float)(n + 1));
    }
    float h[NS];
#pragma unroll
    for (int n = 0; n < NS; n++) h[n] = 0.f;
    float sdt = 0.f;

    __shared__ float sB[32][48];
    const int t_base = c * CHUNK;
    for (int t0 = 0; t0 < CHUNK; t0 += 32) {
        __syncthreads();
        for (int i = threadIdx.x; i < 384; i += 128) {
            int tt = i / 12, j4 = i % 12;
            float4 v = *(const float4*)(xdb +
                ((size_t)b * LQ + t_base + t0 + tt) * 64 + j4 * 4);
            *(float4*)&sB[tt][j4 * 4] = v;
        }
        __syncthreads();
#pragma unroll 4
        for (int tt = 0; tt < 32; tt++) {
            const float* row = sB[tt];
            float v = bias;
#pragma unroll
            for (int r = 0; r < DTR; r++) v += row[r] * w[r];
            const size_t t = (size_t)(t_base + t0 + tt);
            float u = xc[((size_t)b * LQ + t) * DI + d];
            float ev = __expf(v);
            float dt = (v > 15.f) ? v : log1pf(ev);
            sdt += dt;
            float coef = dt * u;
            if (fast) {
                float e = (v > 15.f) ? __expf(-v) : 1.f / (1.f + ev);
                float p = e;
#pragma unroll
                for (int n = 0; n < NS; n++) {
                    h[n] = h[n] * p + coef * row[32 + n];
                    p *= e;
                }
            } else {
#pragma unroll
                for (int n = 0; n < NS; n++)
                    h[n] = h[n] * __expf(dt * a[n]) + coef * row[32 + n];
            }
        }
    }
    sumdt[((size_t)b * NCHUNK + c) * DI + d] = sdt;
#pragma unroll
    for (int n = 0; n < NS; n++)
        hpart[(((size_t)b * NCHUNK + c) * NS + n) * DI + d] = h[n];
}

// ------------------------- scan phase 2 -------------------------------------
__global__ void scan_combine_kernel(const float* __restrict__ hpart,
                                    const float* __restrict__ sumdt,
                                    const float* __restrict__ Alog,
                                    float* __restrict__ hfin) {
    int i = blockIdx.x * blockDim.x + threadIdx.x;
    int d = i & (DI - 1);
    int b = i / DI;
    float a[NS];
    bool fast = true;
#pragma unroll
    for (int n = 0; n < NS; n++) {
        a[n] = -__expf(Alog[(size_t)d * NS + n]);
        fast = fast && (fabsf(a[n] + (float)(n + 1)) < 1e-4f * (float)(n + 1));
    }
    float H[NS];
#pragma unroll
    for (int n = 0; n < NS; n++) H[n] = 0.f;
    for (int c = 0; c < NCHUNK; c++) {
        float s = sumdt[((size_t)b * NCHUNK + c) * DI + d];
        const float* hp = hpart + (((size_t)b * NCHUNK + c) * NS) * DI + d;
        if (fast) {
            float e = __expf(-s), p = e;
#pragma unroll
            for (int n = 0; n < NS; n++) {
                H[n] = H[n] * p + hp[(size_t)n * DI];
                p *= e;
            }
        } else {
#pragma unroll
            for (int n = 0; n < NS; n++)
                H[n] = H[n] * __expf(a[n] * s) + hp[(size_t)n * DI];
        }
    }
#pragma unroll
    for (int n = 0; n < NS; n++) hfin[((size_t)b * NS + n) * DI + d] = H[n];
}

// ------------------------- finale (last-token only) -------------------------
__global__ void xplast_kernel(const float* __restrict__ x,
                              const float* __restrict__ projw,
                              const float* __restrict__ projb,
                              float* __restrict__ xpl) {
    int b = blockIdx.x, m = threadIdx.x;
    __shared__ float xs[DM];
    xs[m] = x[((size_t)b * LQ + (LQ - 1)) * DM + m];
    __syncthreads();
    float s = projb[m];
    const float* wr = projw + (size_t)m * DM;
    for (int k = 0; k < DM; k++) s += xs[k] * wr[k];
    xpl[b * DM + m] = s;
}

__global__ void f2_kernel(const float* __restrict__ xpl,
                          const float* __restrict__ inwf,
                          const float* __restrict__ inwb,
                          float* __restrict__ zf, float* __restrict__ zb,
                          float* __restrict__ xab0) {
    int b = blockIdx.y, kind = blockIdx.x, d = threadIdx.x;
    __shared__ float xs[DM];
    if (d < DM) xs[d] = xpl[b * DM + d];
    __syncthreads();
    const float* wrow;
    if (kind == 0) wrow = inwf + (size_t)(DI + d) * DM;
    else if (kind == 1) wrow = inwb + (size_t)(DI + d) * DM;
    else wrow = inwb + (size_t)d * DM;
    float s = 0.f;
    for (int k = 0; k < DM; k++) s += xs[k] * wrow[k];
    if (kind == 0) zf[b * DI + d] = s;
    else if (kind == 1) zb[b * DI + d] = s;
    else xab0[b * DI + d] = s;
}

__global__ void f3a_kernel(const float* __restrict__ xab0,
                           const float* __restrict__ convwb,
                           const float* __restrict__ convbb,
                           float* __restrict__ xcb0) {
    int i = blockIdx.x * blockDim.x + threadIdx.x;
    int d = i & (DI - 1);
    float t = convwb[d * 4 + 3] * xab0[i] + convbb[d];
    xcb0[i] = silu_f(t);
}

__global__ void f3b_kernel(const float* __restrict__ xcb0,
                           const float* __restrict__ xprojwb,
                           float* __restrict__ xdbb) {
    int b = blockIdx.x, j = threadIdx.x;
    __shared__ float xs[DI];
    for (int k = threadIdx.x; k < DI; k += 64) xs[k] = xcb0[b * DI + k];
    __syncthreads();
    float s = 0.f;
    const float* wr = xprojwb + (size_t)j * DI;
    for (int k = 0; k < DI; k++) s += xs[k] * wr[k];
    xdbb[b * 64 + j] = s;
}

__global__ void f3c_kernel(const float* __restrict__ xdbb,
                           const float* __restrict__ dtwb,
                           const float* __restrict__ dtbb,
                           const float* __restrict__ Db,
                           const float* __restrict__ xcb0,
                           const float* __restrict__ hfin,
                           const float* __restrict__ xdb,
                           const float* __restrict__ xc,
                           const float* __restrict__ Df,
                           const float* __restrict__ zf,
                           const float* __restrict__ zb,
                           float* __restrict__ gf, float* __restrict__ gb) {
    int i = blockIdx.x * blockDim.x + threadIdx.x;
    int d = i & (DI - 1);
    int b = i / DI;
    const float* xb = xdbb + b * 64;
    float v = dtbb[d];
#pragma unroll
    for (int r = 0; r < DTR; r++) v += xb[r] * dtwb[(size_t)d * DTR + r];
    float ev = __expf(v);
    float dt = (v > 15.f) ? v : log1pf(ev);
    float S = 0.f;
#pragma unroll
    for (int n = 0; n < NS; n++) S += xb[32 + n] * xb[48 + n];
    float u = xcb0[i];
    float yb = dt * u * S + u * Db[d];
    gb[i] = yb * silu_f(zb[i]);
    const float* Crow = xdb + ((size_t)b * LQ + LQ - 1) * 64 + 48;
    float yf = 0.f;
#pragma unroll
    for (int n = 0; n < NS; n++)
        yf += hfin[((size_t)b * NS + n) * DI + d] * Crow[n];
    yf += xc[((size_t)b * LQ + LQ - 1) * DI + d] * Df[d];
    gf[i] = yf * silu_f(zf[i]);
}

__global__ void f4_kernel(const float* __restrict__ gf,
                          const float* __restrict__ gb,
                          const float* __restrict__ outwf,
                          const float* __restrict__ outwb,
                          float* __restrict__ outf, float* __restrict__ outb) {
    int side = blockIdx.x, b = blockIdx.y;
    int m = threadIdx.x;
    __shared__ float gs[DI];
    const float* g = side ? gb : gf;
    for (int k = m; k < DI; k += DM) gs[k] = g[b * DI + k];
    __syncthreads();
    const float* wr = (side ? outwb : outwf) + (size_t)m * DI;
    float s = 0.f;
    for (int k = 0; k < DI; k++) s += gs[k] * wr[k];
    (side ? outb : outf)[b * DM + m] = s;
}

__global__ void f5_kernel(const float* __restrict__ outf,
                          const float* __restrict__ outb,
                          const float* __restrict__ fw,
                          const float* __restrict__ fb,
                          const float* __restrict__ lng,
                          const float* __restrict__ lnb,
                          float* __restrict__ out) {
    int b = blockIdx.x, m = threadIdx.x;
    __shared__ float cat[2 * DM];
    __shared__ float red[DM];
    cat[m] = outf[b * DM + m];
    cat[DM + m] = outb[b * DM + m];
    __syncthreads();
    float r = fb[m];
    const float* wr = fw + (size_t)m * 2 * DM;
    for (int j = 0; j < 2 * DM; j++) r += cat[j] * wr[j];
    red[m] = r;
    __syncthreads();
    for (int s = 256; s > 0; s >>= 1) {
        if (m < s) red[m] += red[m + s];
        __syncthreads();
    }
    float mu = red[0] * (1.f / DM);
    __syncthreads();
    float dv = r - mu;
    red[m] = dv * dv;
    __syncthreads();
    for (int s = 256; s > 0; s >>= 1) {
        if (m < s) red[m] += red[m + s];
        __syncthreads();
    }
    float var = red[0] * (1.f / DM);
    out[b * DM + m] = dv * rsqrtf(var + 1e-5f) * lng[m] + lnb[m];
}

// ------------------------- launch ------------------------------------------
extern "C" void kernel_launch(void* const* d_in, const int* in_sizes, int n_in,
                              void* d_out, int out_size) {
    (void)in_sizes; (void)n_in; (void)out_size;
    const float* x        = (const float*)d_in[0];
    const float* proj_w   = (const float*)d_in[1];
    const float* proj_b   = (const float*)d_in[2];
    const float* in_w_f   = (const float*)d_in[3];
    const float* conv_w_f = (const float*)d_in[4];
    const float* conv_b_f = (const float*)d_in[5];
    const float* xproj_w_f= (const float*)d_in[6];
    const float* dt_w_f   = (const float*)d_in[7];
    const float* dt_b_f   = (const float*)d_in[8];
    const float* A_log_f  = (const float*)d_in[9];
    const float* D_f      = (const float*)d_in[10];
    const float* out_w_f  = (const float*)d_in[11];
    const float* in_w_b   = (const float*)d_in[12];
    const float* conv_w_b = (const float*)d_in[13];
    const float* conv_b_b = (const float*)d_in[14];
    const float* xproj_w_b= (const float*)d_in[15];
    const float* dt_w_b   = (const float*)d_in[16];
    const float* dt_b_b   = (const float*)d_in[17];
    const float* A_log_b  = (const float*)d_in[18];
    const float* D_b      = (const float*)d_in[19];
    const float* out_w_b  = (const float*)d_in[20];
    const float* fusion_w = (const float*)d_in[21];
    const float* fusion_b = (const float*)d_in[22];
    const float* ln_g     = (const float*)d_in[23];
    const float* ln_b     = (const float*)d_in[24];
    float* out = (float*)d_out;

    float *W, *c, *xa, *xc, *xdb, *hpart, *sumdt, *hfin, *xpl;
    float *zf, *zb, *xab0, *xcb0, *xdbb, *gf, *gb, *outf, *outb;
    cudaGetSymbolAddress((void**)&W, g_W);
    cudaGetSymbolAddress((void**)&c, g_c);
    cudaGetSymbolAddress((void**)&xa, g_xa);
    cudaGetSymbolAddress((void**)&xc, g_xc);
    cudaGetSymbolAddress((void**)&xdb, g_xdb);
    cudaGetSymbolAddress((void**)&hpart, g_hpart);
    cudaGetSymbolAddress((void**)&sumdt, g_sumdt);
    cudaGetSymbolAddress((void**)&hfin, g_hfin);
    cudaGetSymbolAddress((void**)&xpl, g_xplast);
    cudaGetSymbolAddress((void**)&zf, g_zf);
    cudaGetSymbolAddress((void**)&zb, g_zb);
    cudaGetSymbolAddress((void**)&xab0, g_xab0);
    cudaGetSymbolAddress((void**)&xcb0, g_xcb0);
    cudaGetSymbolAddress((void**)&xdbb, g_xdbb);
    cudaGetSymbolAddress((void**)&gf, g_gf);
    cudaGetSymbolAddress((void**)&gb, g_gb);
    cudaGetSymbolAddress((void**)&outf, g_outf);
    cudaGetSymbolAddress((void**)&outb, g_outb);

    const int M = BQ * LQ; // 32768

    // 1. fold weights
    fold_kernel<<<dim3(DM / 16, DI / 16), dim3(16, 16)>>>(in_w_f, proj_w, W);
    foldc_kernel<<<DI / 256, 256>>>(in_w_f, proj_b, c);
    // 2. xa = x @ W^T + c   (f32x2 packed FMA)
    sgemm128_nt<<<dim3(DI / 128, M / 128), 256>>>(x, W, c, xa, M, DI, DM);
    // 3. conv + silu
    conv_silu_kernel<<<(M * (DI / 4)) / 256, 256>>>(xa, conv_w_f, conv_b_f, xc);
    // 4. xproj (f32x2)
    sgemm_n64<<<M / 128, 256>>>(xc, xproj_w_f, xdb, M, DI);
    // 5. scan
    scan_chunk_kernel<<<dim3(DI / 128, NCHUNK, BQ), 128>>>(
        xc, xdb, dt_w_f, dt_b_f, A_log_f, hpart, sumdt);
    scan_combine_kernel<<<(BQ * DI) / 128, 128>>>(hpart, sumdt, A_log_f, hfin);
    // 6. finale (last-token only)
    xplast_kernel<<<BQ, DM>>>(x, proj_w, proj_b, xpl);
    f2_kernel<<<dim3(3, BQ), DI>>>(xpl, in_w_f, in_w_b, zf, zb, xab0);
    f3a_kernel<<<(BQ * DI) / 256, 256>>>(xab0, conv_w_b, conv_b_b, xcb0);
    f3b_kernel<<<BQ, 64>>>(xcb0, xproj_w_b, xdbb);
    f3c_kernel<<<(BQ * DI) / 256, 256>>>(xdbb, dt_w_b, dt_b_b, D_b, xcb0,
                                          hfin, xdb, xc, D_f, zf, zb, gf, gb);
    f4_kernel<<<dim3(2, BQ), DM>>>(gf, gb, out_w_f, out_w_b, outf, outb);
    f5_kernel<<<BQ, DM>>>(outf, outb, fusion_w, fusion_b, ln_g, ln_b, out);
}

// round 14
// speedup vs baseline: 1.2215x; 1.2215x over previous
#include <cuda_runtime.h>
#include <cuda_bf16.h>
#include <cstdint>
#include <cstdio>

#define BQ 8
#define LQ 4096
#define DM 512
#define DI 1024
#define NS 16
#define DTR 32
#define CHUNK 256
#define NCHUNK (LQ / CHUNK) /* 16 */

// ------------------------- scratch (device globals; no allocs) -------------
__device__ float g_W[DI * DM];
__device__ float g_c[DI];
__device__ float g_xa[(size_t)BQ * LQ * DI];
__device__ float g_xc[(size_t)BQ * LQ * DI];
__device__ float g_xdb[(size_t)BQ * LQ * 64];
__device__ float g_hpart[BQ * NCHUNK * NS * DI];
__device__ float g_sumdt[BQ * NCHUNK * DI];
__device__ float g_hfin[BQ * NS * DI];
__device__ float g_xplast[BQ * DM];
__device__ float g_zf[BQ * DI];
__device__ float g_zb[BQ * DI];
__device__ float g_xab0[BQ * DI];
__device__ float g_xcb0[BQ * DI];
__device__ float g_xdbb[BQ * 64];
__device__ float g_gf[BQ * DI];
__device__ float g_gb[BQ * DI];
__device__ float g_outf[BQ * DM];
__device__ float g_outb[BQ * DM];

__device__ __forceinline__ float silu_f(float x) {
    return x / (1.0f + __expf(-x));
}

// ------------------------- 3x-bf16 tensor GEMM (mma.m16n8k16) ---------------
// C[m,n] = sum_k A[m,k] * Bw[n,k] (+ bias[n] if bias != null)
// A: MxK fp32 row-major.  Bw: NwxK fp32 row-major (rows >= Nw read as zero).
// On-the-fly split: x = hi + lo (both bf16); D = Ah*Bh + Al*Bh + Ah*Bl.
// Block tile 128x128, BK=16, 256 thr = 8 warps (2m x 4n), warp tile 64x32.
#define MMA_BF16(c, a0, a1, a2, a3, b0, b1)                                   \
    asm volatile(                                                             \
        "mma.sync.aligned.m16n8k16.row.col.f32.bf16.bf16.f32 "                \
        "{%0,%1,%2,%3}, {%4,%5,%6,%7}, {%8,%9}, {%0,%1,%2,%3};"               \
        : "+f"((c)[0]), "+f"((c)[1]), "+f"((c)[2]), "+f"((c)[3])              \
        : "r"(a0), "r"(a1), "r"(a2), "r"(a3), "r"(b0), "r"(b1))

__device__ __forceinline__ void split2pack(float x0, float x1,
                                           uint32_t& hp, uint32_t& lp) {
    __nv_bfloat16 h0 = __float2bfloat16(x0);
    __nv_bfloat16 h1 = __float2bfloat16(x1);
    __nv_bfloat16 l0 = __float2bfloat16(x0 - __bfloat162float(h0));
    __nv_bfloat16 l1 = __float2bfloat16(x1 - __bfloat162float(h1));
    hp = ((uint32_t)__bfloat16_as_ushort(h1) << 16) | __bfloat16_as_ushort(h0);
    lp = ((uint32_t)__bfloat16_as_ushort(l1) << 16) | __bfloat16_as_ushort(l0);
}

__global__ __launch_bounds__(256) void bf16gemm3x_nt(
    const float* __restrict__ A, const float* __restrict__ Bw,
    const float* __restrict__ bias, float* __restrict__ C,
    int M, int N, int K, int Nw) {
    // smem: uint32 bf16-pairs, [stage][k-pair(8) = 16 k][m], pad 136
    __shared__ uint32_t Ah[2][8][136], Al[2][8][136];
    __shared__ uint32_t Bh[2][8][136], Bl[2][8][136];
    const int tid = threadIdx.x;
    const int bm = blockIdx.y * 128, bn = blockIdx.x * 128;
    const int lane = tid & 31, warp = tid >> 5;
    const int wm = (warp & 1) * 64, wn = (warp >> 1) * 32;
    const int lr = tid >> 1;          // 0..127 tile row
    const int lc8 = (tid & 1) * 8;    // k sub-block: 0 or 8
    const int kpb = lc8 >> 1;         // pair base: 0 or 4
    const float* Ap = A + (size_t)(bm + lr) * K + lc8;
    const int bRow = bn + lr;
    const bool bOk = bRow < Nw;
    const float* Bp = Bw + (size_t)(bOk ? bRow : 0) * K + lc8;

    float acc[4][4][4];
#pragma unroll
    for (int mt = 0; mt < 4; mt++)
#pragma unroll
        for (int nt = 0; nt < 4; nt++)
#pragma unroll
            for (int r = 0; r < 4; r++) acc[mt][nt][r] = 0.f;

    const float4 z4 = make_float4(0.f, 0.f, 0.f, 0.f);
    float4 av0 = *(const float4*)Ap;
    float4 av1 = *(const float4*)(Ap + 4);
    float4 bv0 = bOk ? *(const float4*)Bp : z4;
    float4 bv1 = bOk ? *(const float4*)(Bp + 4) : z4;
    int cur = 0;
    const int kq = lane & 3, gq = lane >> 2;

    for (int k0 = 0; k0 < K; k0 += 16) {
        {
            uint32_t hp, lp;
            split2pack(av0.x, av0.y, hp, lp);
            Ah[cur][kpb + 0][lr] = hp; Al[cur][kpb + 0][lr] = lp;
            split2pack(av0.z, av0.w, hp, lp);
            Ah[cur][kpb + 1][lr] = hp; Al[cur][kpb + 1][lr] = lp;
            split2pack(av1.x, av1.y, hp, lp);
            Ah[cur][kpb + 2][lr] = hp; Al[cur][kpb + 2][lr] = lp;
            split2pack(av1.z, av1.w, hp, lp);
            Ah[cur][kpb + 3][lr] = hp; Al[cur][kpb + 3][lr] = lp;
            split2pack(bv0.x, bv0.y, hp, lp);
            Bh[cur][kpb + 0][lr] = hp; Bl[cur][kpb + 0][lr] = lp;
            split2pack(bv0.z, bv0.w, hp, lp);
            Bh[cur][kpb + 1][lr] = hp; Bl[cur][kpb + 1][lr] = lp;
            split2pack(bv1.x, bv1.y, hp, lp);
            Bh[cur][kpb + 2][lr] = hp; Bl[cur][kpb + 2][lr] = lp;
            split2pack(bv1.z, bv1.w, hp, lp);
            Bh[cur][kpb + 3][lr] = hp; Bl[cur][kpb + 3][lr] = lp;
        }
        if (k0 + 16 < K) {
            av0 = *(const float4*)(Ap + k0 + 16);
            av1 = *(const float4*)(Ap + k0 + 20);
            bv0 = bOk ? *(const float4*)(Bp + k0 + 16) : z4;
            bv1 = bOk ? *(const float4*)(Bp + k0 + 20) : z4;
        }
        __syncthreads();

        uint32_t bh[4][2], bl[4][2];
#pragma unroll
        for (int nt = 0; nt < 4; nt++) {
            int nb = wn + nt * 8 + gq;
            bh[nt][0] = Bh[cur][kq][nb];
            bh[nt][1] = Bh[cur][kq + 4][nb];
            bl[nt][0] = Bl[cur][kq][nb];
            bl[nt][1] = Bl[cur][kq + 4][nb];
        }
#pragma unroll
        for (int mt = 0; mt < 4; mt++) {
            int mb = wm + mt * 16 + gq;
            uint32_t ah0 = Ah[cur][kq][mb];
            uint32_t ah1 = Ah[cur][kq][mb + 8];
            uint32_t ah2 = Ah[cur][kq + 4][mb];
            uint32_t ah3 = Ah[cur][kq + 4][mb + 8];
            uint32_t al0 = Al[cur][kq][mb];
            uint32_t al1 = Al[cur][kq][mb + 8];
            uint32_t al2 = Al[cur][kq + 4][mb];
            uint32_t al3 = Al[cur][kq + 4][mb + 8];
#pragma unroll
            for (int nt = 0; nt < 4; nt++) {
                MMA_BF16(acc[mt][nt], ah0, ah1, ah2, ah3, bh[nt][0], bh[nt][1]);
                MMA_BF16(acc[mt][nt], al0, al1, al2, al3, bh[nt][0], bh[nt][1]);
                MMA_BF16(acc[mt][nt], ah0, ah1, ah2, ah3, bl[nt][0], bl[nt][1]);
            }
        }
        __syncthreads();
        cur ^= 1;
    }

#pragma unroll
    for (int mt = 0; mt < 4; mt++) {
#pragma unroll
        for (int nt = 0; nt < 4; nt++) {
            int row = bm + wm + mt * 16 + gq;
            int col = bn + wn + nt * 8 + kq * 2;
            if (col < N) {
                float b0 = bias ? bias[col] : 0.f;
                float b1 = bias ? bias[col + 1] : 0.f;
                C[(size_t)row * N + col] = acc[mt][nt][0] + b0;
                C[(size_t)row * N + col + 1] = acc[mt][nt][1] + b1;
                C[(size_t)(row + 8) * N + col] = acc[mt][nt][2] + b0;
                C[(size_t)(row + 8) * N + col + 1] = acc[mt][nt][3] + b1;
            }
        }
    }
}

// ------------------------- weight fold --------------------------------------
__global__ void fold_kernel(const float* __restrict__ inwA,
                            const float* __restrict__ projw,
                            float* __restrict__ W) {
    __shared__ float As[16][16];
    __shared__ float Bs[16][17];
    int tx = threadIdx.x, ty = threadIdx.y;
    int m = blockIdx.y * 16 + ty;
    int n = blockIdx.x * 16 + tx;
    float acc = 0.f;
    for (int k0 = 0; k0 < DM; k0 += 16) {
        As[ty][tx] = inwA[(size_t)m * DM + k0 + tx];
        Bs[ty][tx] = projw[(size_t)(k0 + ty) * DM + n];
        __syncthreads();
#pragma unroll
        for (int k = 0; k < 16; k++) acc += As[ty][k] * Bs[k][tx];
        __syncthreads();
    }
    W[(size_t)m * DM + n] = acc;
}

__global__ void foldc_kernel(const float* __restrict__ inwA,
                             const float* __restrict__ projb,
                             float* __restrict__ c) {
    int m = blockIdx.x * blockDim.x + threadIdx.x;
    if (m >= DI) return;
    float s = 0.f;
    for (int k = 0; k < DM; k++) s += inwA[(size_t)m * DM + k] * projb[k];
    c[m] = s;
}

// ------------------------- causal depthwise conv (4 taps) + silu ------------
__global__ void conv_silu_kernel(const float* __restrict__ xa,
                                 const float* __restrict__ convw,
                                 const float* __restrict__ convb,
                                 float* __restrict__ xc) {
    size_t i = (size_t)blockIdx.x * blockDim.x + threadIdx.x;
    int d4 = (int)(i & 255);
    size_t bt = i >> 8;
    int t = (int)(bt & (LQ - 1));
    const float4* xa4 = (const float4*)xa;
    const float4* w4 = (const float4*)convw;
    float4 w0 = w4[d4 * 4 + 0], w1 = w4[d4 * 4 + 1];
    float4 w2 = w4[d4 * 4 + 2], w3 = w4[d4 * 4 + 3];
    float4 bias = ((const float4*)convb)[d4];
    float4 z4 = make_float4(0.f, 0.f, 0.f, 0.f);
    float4 xv3 = xa4[bt * 256 + d4];
    float4 xv2 = (t >= 1) ? xa4[(bt - 1) * 256 + d4] : z4;
    float4 xv1 = (t >= 2) ? xa4[(bt - 2) * 256 + d4] : z4;
    float4 xv0 = (t >= 3) ? xa4[(bt - 3) * 256 + d4] : z4;
    float o0 = w0.x * xv0.x + w0.y * xv1.x + w0.z * xv2.x + w0.w * xv3.x + bias.x;
    float o1 = w1.x * xv0.y + w1.y * xv1.y + w1.z * xv2.y + w1.w * xv3.y + bias.y;
    float o2 = w2.x * xv0.z + w2.y * xv1.z + w2.z * xv2.z + w2.w * xv3.z + bias.z;
    float o3 = w3.x * xv0.w + w3.y * xv1.w + w3.z * xv2.w + w3.w * xv3.w + bias.w;
    float4 out = make_float4(silu_f(o0), silu_f(o1), silu_f(o2), silu_f(o3));
    ((float4*)xc)[bt * 256 + d4] = out;
}

// ------------------------- chunked selective scan, phase 1 ------------------
__global__ __launch_bounds__(128) void scan_chunk_kernel(
    const float* __restrict__ xc, const float* __restrict__ xdb,
    const float* __restrict__ dtw, const float* __restrict__ dtb,
    const float* __restrict__ Alog,
    float* __restrict__ hpart, float* __restrict__ sumdt) {
    const int d = blockIdx.x * 128 + threadIdx.x;
    const int c = blockIdx.y, b = blockIdx.z;
    float w[DTR];
#pragma unroll
    for (int r = 0; r < DTR; r++) w[r] = dtw[(size_t)d * DTR + r];
    const float bias = dtb[d];
    float a[NS];
    bool fast = true;
#pragma unroll
    for (int n = 0; n < NS; n++) {
        a[n] = -__expf(Alog[(size_t)d * NS + n]);
        fast = fast && (fabsf(a[n] + (float)(n + 1)) < 1e-4f * (float)(n + 1));
    }
    float h[NS];
#pragma unroll
    for (int n = 0; n < NS; n++) h[n] = 0.f;
    float sdt = 0.f;

    __shared__ float sB[32][48];
    const int t_base = c * CHUNK;
    for (int t0 = 0; t0 < CHUNK; t0 += 32) {
        __syncthreads();
        for (int i = threadIdx.x; i < 384; i += 128) {
            int tt = i / 12, j4 = i % 12;
            float4 v = *(const float4*)(xdb +
                ((size_t)b * LQ + t_base + t0 + tt) * 64 + j4 * 4);
            *(float4*)&sB[tt][j4 * 4] = v;
        }
        __syncthreads();
#pragma unroll 4
        for (int tt = 0; tt < 32; tt++) {
            const float* row = sB[tt];
            float v = bias;
#pragma unroll
            for (int r = 0; r < DTR; r++) v += row[r] * w[r];
            const size_t t = (size_t)(t_base + t0 + tt);
            float u = xc[((size_t)b * LQ + t) * DI + d];
            float ev = __expf(v);
            float dt = (v > 15.f) ? v : log1pf(ev);
            sdt += dt;
            float coef = dt * u;
            if (fast) {
                float e = (v > 15.f) ? __expf(-v) : 1.f / (1.f + ev);
                float p = e;
#pragma unroll
                for (int n = 0; n < NS; n++) {
                    h[n] = h[n] * p + coef * row[32 + n];
                    p *= e;
                }
            } else {
#pragma unroll
                for (int n = 0; n < NS; n++)
                    h[n] = h[n] * __expf(dt * a[n]) + coef * row[32 + n];
            }
        }
    }
    sumdt[((size_t)b * NCHUNK + c) * DI + d] = sdt;
#pragma unroll
    for (int n = 0; n < NS; n++)
        hpart[(((size_t)b * NCHUNK + c) * NS + n) * DI + d] = h[n];
}

// ------------------------- scan phase 2 -------------------------------------
__global__ void scan_combine_kernel(const float* __restrict__ hpart,
                                    const float* __restrict__ sumdt,
                                    const float* __restrict__ Alog,
                                    float* __restrict__ hfin) {
    int i = blockIdx.x * blockDim.x + threadIdx.x;
    int d = i & (DI - 1);
    int b = i / DI;
    float a[NS];
    bool fast = true;
#pragma unroll
    for (int n = 0; n < NS; n++) {
        a[n] = -__expf(Alog[(size_t)d * NS + n]);
        fast = fast && (fabsf(a[n] + (float)(n + 1)) < 1e-4f * (float)(n + 1));
    }
    float H[NS];
#pragma unroll
    for (int n = 0; n < NS; n++) H[n] = 0.f;
    for (int c = 0; c < NCHUNK; c++) {
        float s = sumdt[((size_t)b * NCHUNK + c) * DI + d];
        const float* hp = hpart + (((size_t)b * NCHUNK + c) * NS) * DI + d;
        if (fast) {
            float e = __expf(-s), p = e;
#pragma unroll
            for (int n = 0; n < NS; n++) {
                H[n] = H[n] * p + hp[(size_t)n * DI];
                p *= e;
            }
        } else {
#pragma unroll
            for (int n = 0; n < NS; n++)
                H[n] = H[n] * __expf(a[n] * s) + hp[(size_t)n * DI];
        }
    }
#pragma unroll
    for (int n = 0; n < NS; n++) hfin[((size_t)b * NS + n) * DI + d] = H[n];
}

// ------------------------- finale (last-token only) -------------------------
__global__ void xplast_kernel(const float* __restrict__ x,
                              const float* __restrict__ projw,
                              const float* __restrict__ projb,
                              float* __restrict__ xpl) {
    int b = blockIdx.x, m = threadIdx.x;
    __shared__ float xs[DM];
    xs[m] = x[((size_t)b * LQ + (LQ - 1)) * DM + m];
    __syncthreads();
    float s = projb[m];
    const float* wr = projw + (size_t)m * DM;
    for (int k = 0; k < DM; k++) s += xs[k] * wr[k];
    xpl[b * DM + m] = s;
}

__global__ void f2_kernel(const float* __restrict__ xpl,
                          const float* __restrict__ inwf,
                          const float* __restrict__ inwb,
                          float* __restrict__ zf, float* __restrict__ zb,
                          float* __restrict__ xab0) {
    int b = blockIdx.y, kind = blockIdx.x, d = threadIdx.x;
    __shared__ float xs[DM];
    if (d < DM) xs[d] = xpl[b * DM + d];
    __syncthreads();
    const float* wrow;
    if (kind == 0) wrow = inwf + (size_t)(DI + d) * DM;
    else if (kind == 1) wrow = inwb + (size_t)(DI + d) * DM;
    else wrow = inwb + (size_t)d * DM;
    float s = 0.f;
    for (int k = 0; k < DM; k++) s += xs[k] * wrow[k];
    if (kind == 0) zf[b * DI + d] = s;
    else if (kind == 1) zb[b * DI + d] = s;
    else xab0[b * DI + d] = s;
}

__global__ void f3a_kernel(const float* __restrict__ xab0,
                           const float* __restrict__ convwb,
                           const float* __restrict__ convbb,
                           float* __restrict__ xcb0) {
    int i = blockIdx.x * blockDim.x + threadIdx.x;
    int d = i & (DI - 1);
    float t = convwb[d * 4 + 3] * xab0[i] + convbb[d];
    xcb0[i] = silu_f(t);
}

__global__ void f3b_kernel(const float* __restrict__ xcb0,
                           const float* __restrict__ xprojwb,
                           float* __restrict__ xdbb) {
    int b = blockIdx.x, j = threadIdx.x;
    __shared__ float xs[DI];
    for (int k = threadIdx.x; k < DI; k += 64) xs[k] = xcb0[b * DI + k];
    __syncthreads();
    float s = 0.f;
    const float* wr = xprojwb + (size_t)j * DI;
    for (int k = 0; k < DI; k++) s += xs[k] * wr[k];
    xdbb[b * 64 + j] = s;
}

__global__ void f3c_kernel(const float* __restrict__ xdbb,
                           const float* __restrict__ dtwb,
                           const float* __restrict__ dtbb,
                           const float* __restrict__ Db,
                           const float* __restrict__ xcb0,
                           const float* __restrict__ hfin,
                           const float* __restrict__ xdb,
                           const float* __restrict__ xc,
                           const float* __restrict__ Df,
                           const float* __restrict__ zf,
                           const float* __restrict__ zb,
                           float* __restrict__ gf, float* __restrict__ gb) {
    int i = blockIdx.x * blockDim.x + threadIdx.x;
    int d = i & (DI - 1);
    int b = i / DI;
    const float* xb = xdbb + b * 64;
    float v = dtbb[d];
#pragma unroll
    for (int r = 0; r < DTR; r++) v += xb[r] * dtwb[(size_t)d * DTR + r];
    float ev = __expf(v);
    float dt = (v > 15.f) ? v : log1pf(ev);
    float S = 0.f;
#pragma unroll
    for (int n = 0; n < NS; n++) S += xb[32 + n] * xb[48 + n];
    float u = xcb0[i];
    float yb = dt * u * S + u * Db[d];
    gb[i] = yb * silu_f(zb[i]);
    const float* Crow = xdb + ((size_t)b * LQ + LQ - 1) * 64 + 48;
    float yf = 0.f;
#pragma unroll
    for (int n = 0; n < NS; n++)
        yf += hfin[((size_t)b * NS + n) * DI + d] * Crow[n];
    yf += xc[((size_t)b * LQ + LQ - 1) * DI + d] * Df[d];
    gf[i] = yf * silu_f(zf[i]);
}

__global__ void f4_kernel(const float* __restrict__ gf,
                          const float* __restrict__ gb,
                          const float* __restrict__ outwf,
                          const float* __restrict__ outwb,
                          float* __restrict__ outf, float* __restrict__ outb) {
    int side = blockIdx.x, b = blockIdx.y;
    int m = threadIdx.x;
    __shared__ float gs[DI];
    const float* g = side ? gb : gf;
    for (int k = m; k < DI; k += DM) gs[k] = g[b * DI + k];
    __syncthreads();
    const float* wr = (side ? outwb : outwf) + (size_t)m * DI;
    float s = 0.f;
    for (int k = 0; k < DI; k++) s += gs[k] * wr[k];
    (side ? outb : outf)[b * DM + m] = s;
}

__global__ void f5_kernel(const float* __restrict__ outf,
                          const float* __restrict__ outb,
                          const float* __restrict__ fw,
                          const float* __restrict__ fb,
                          const float* __restrict__ lng,
                          const float* __restrict__ lnb,
                          float* __restrict__ out) {
    int b = blockIdx.x, m = threadIdx.x;
    __shared__ float cat[2 * DM];
    __shared__ float red[DM];
    cat[m] = outf[b * DM + m];
    cat[DM + m] = outb[b * DM + m];
    __syncthreads();
    float r = fb[m];
    const float* wr = fw + (size_t)m * 2 * DM;
    for (int j = 0; j < 2 * DM; j++) r += cat[j] * wr[j];
    red[m] = r;
    __syncthreads();
    for (int s = 256; s > 0; s >>= 1) {
        if (m < s) red[m] += red[m + s];
        __syncthreads();
    }
    float mu = red[0] * (1.f / DM);
    __syncthreads();
    float dv = r - mu;
    red[m] = dv * dv;
    __syncthreads();
    for (int s = 256; s > 0; s >>= 1) {
        if (m < s) red[m] += red[m + s];
        __syncthreads();
    }
    float var = red[0] * (1.f / DM);
    out[b * DM + m] = dv * rsqrtf(var + 1e-5f) * lng[m] + lnb[m];
}

// ------------------------- launch ------------------------------------------
extern "C" void kernel_launch(void* const* d_in, const int* in_sizes, int n_in,
                              void* d_out, int out_size) {
    (void)in_sizes; (void)n_in; (void)out_size;
    const float* x        = (const float*)d_in[0];
    const float* proj_w   = (const float*)d_in[1];
    const float* proj_b   = (const float*)d_in[2];
    const float* in_w_f   = (const float*)d_in[3];
    const float* conv_w_f = (const float*)d_in[4];
    const float* conv_b_f = (const float*)d_in[5];
    const float* xproj_w_f= (const float*)d_in[6];
    const float* dt_w_f   = (const float*)d_in[7];
    const float* dt_b_f   = (const float*)d_in[8];
    const float* A_log_f  = (const float*)d_in[9];
    const float* D_f      = (const float*)d_in[10];
    const float* out_w_f  = (const float*)d_in[11];
    const float* in_w_b   = (const float*)d_in[12];
    const float* conv_w_b = (const float*)d_in[13];
    const float* conv_b_b = (const float*)d_in[14];
    const float* xproj_w_b= (const float*)d_in[15];
    const float* dt_w_b   = (const float*)d_in[16];
    const float* dt_b_b   = (const float*)d_in[17];
    const float* A_log_b  = (const float*)d_in[18];
    const float* D_b      = (const float*)d_in[19];
    const float* out_w_b  = (const float*)d_in[20];
    const float* fusion_w = (const float*)d_in[21];
    const float* fusion_b = (const float*)d_in[22];
    const float* ln_g     = (const float*)d_in[23];
    const float* ln_b     = (const float*)d_in[24];
    float* out = (float*)d_out;

    float *W, *c, *xa, *xc, *xdb, *hpart, *sumdt, *hfin, *xpl;
    float *zf, *zb, *xab0, *xcb0, *xdbb, *gf, *gb, *outf, *outb;
    cudaGetSymbolAddress((void**)&W, g_W);
    cudaGetSymbolAddress((void**)&c, g_c);
    cudaGetSymbolAddress((void**)&xa, g_xa);
    cudaGetSymbolAddress((void**)&xc, g_xc);
    cudaGetSymbolAddress((void**)&xdb, g_xdb);
    cudaGetSymbolAddress((void**)&hpart, g_hpart);
    cudaGetSymbolAddress((void**)&sumdt, g_sumdt);
    cudaGetSymbolAddress((void**)&hfin, g_hfin);
    cudaGetSymbolAddress((void**)&xpl, g_xplast);
    cudaGetSymbolAddress((void**)&zf, g_zf);
    cudaGetSymbolAddress((void**)&zb, g_zb);
    cudaGetSymbolAddress((void**)&xab0, g_xab0);
    cudaGetSymbolAddress((void**)&xcb0, g_xcb0);
    cudaGetSymbolAddress((void**)&xdbb, g_xdbb);
    cudaGetSymbolAddress((void**)&gf, g_gf);
    cudaGetSymbolAddress((void**)&gb, g_gb);
    cudaGetSymbolAddress((void**)&outf, g_outf);
    cudaGetSymbolAddress((void**)&outb, g_outb);

    const int M = BQ * LQ; // 32768

    // 1. fold weights
    fold_kernel<<<dim3(DM / 16, DI / 16), dim3(16, 16)>>>(in_w_f, proj_w, W);
    foldc_kernel<<<DI / 256, 256>>>(in_w_f, proj_b, c);
    // 2. xa = x @ W^T + c   (3x-bf16 mma.m16n8k16)
    bf16gemm3x_nt<<<dim3(DI / 128, M / 128), 256>>>(x, W, c, xa,
                                                    M, DI, DM, DI);
    // 3. conv + silu
    conv_silu_kernel<<<(M * (DI / 4)) / 256, 256>>>(xa, conv_w_f, conv_b_f, xc);
    // 4. xproj (3x-bf16; N=64 cols within one 128-wide tile)
    bf16gemm3x_nt<<<dim3(1, M / 128), 256>>>(xc, xproj_w_f, nullptr, xdb,
                                             M, 64, DI, 64);
    // 5. scan
    scan_chunk_kernel<<<dim3(DI / 128, NCHUNK, BQ), 128>>>(
        xc, xdb, dt_w_f, dt_b_f, A_log_f, hpart, sumdt);
    scan_combine_kernel<<<(BQ * DI) / 128, 128>>>(hpart, sumdt, A_log_f, hfin);
    // 6. finale (last-token only)
    xplast_kernel<<<BQ, DM>>>(x, proj_w, proj_b, xpl);
    f2_kernel<<<dim3(3, BQ), DI>>>(xpl, in_w_f, in_w_b, zf, zb, xab0);
    f3a_kernel<<<(BQ * DI) / 256, 256>>>(xab0, conv_w_b, conv_b_b, xcb0);
    f3b_kernel<<<BQ, 64>>>(xcb0, xproj_w_b, xdbb);
    f3c_kernel<<<(BQ * DI) / 256, 256>>>(xdbb, dt_w_b, dt_b_b, D_b, xcb0,
                                          hfin, xdb, xc, D_f, zf, zb, gf, gb);
    f4_kernel<<<dim3(2, BQ), DM>>>(gf, gb, out_w_f, out_w_b, outf, outb);
    f5_kernel<<<BQ, DM>>>(outf, outb, fusion_w, fusion_b, ln_g, ln_b, out);
}

// round 17
// speedup vs baseline: 1.2316x; 1.0083x over previous
#include <cuda_runtime.h>
#include <cuda_bf16.h>
#include <cstdint>
#include <cstdio>

#define BQ 8
#define LQ 4096
#define DM 512
#define DI 1024
#define NS 16
#define DTR 32
#define CHUNK 256
#define NCHUNK (LQ / CHUNK) /* 16 */

// ------------------------- scratch (device globals; no allocs) -------------
__device__ float g_W[DI * DM];
__device__ float g_c[DI];
__device__ float g_xa[(size_t)BQ * LQ * DI];
__device__ float g_xc[(size_t)BQ * LQ * DI];
__device__ float g_xdb[(size_t)BQ * LQ * 64];
__device__ float g_hpart[BQ * NCHUNK * NS * DI];
__device__ float g_sumdt[BQ * NCHUNK * DI];
__device__ float g_hfin[BQ * NS * DI];
__device__ float g_xplast[BQ * DM];
__device__ float g_zf[BQ * DI];
__device__ float g_zb[BQ * DI];
__device__ float g_xab0[BQ * DI];
__device__ float g_xcb0[BQ * DI];
__device__ float g_xdbb[BQ * 64];
__device__ float g_gf[BQ * DI];
__device__ float g_gb[BQ * DI];
__device__ float g_outf[BQ * DM];
__device__ float g_outb[BQ * DM];
// pre-split bf16 operand buffers
__device__ __nv_bfloat16 g_xhi[(size_t)BQ * LQ * DM];
__device__ __nv_bfloat16 g_xlo[(size_t)BQ * LQ * DM];
__device__ __nv_bfloat16 g_Whi[DI * DM];
__device__ __nv_bfloat16 g_Wlo[DI * DM];
__device__ __nv_bfloat16 g_xchi[(size_t)BQ * LQ * DI];
__device__ __nv_bfloat16 g_xclo[(size_t)BQ * LQ * DI];
__device__ __nv_bfloat16 g_xpwhi[64 * DI];
__device__ __nv_bfloat16 g_xpwlo[64 * DI];

__device__ __forceinline__ float silu_f(float x) {
    return x / (1.0f + __expf(-x));
}

__device__ __forceinline__ void split2pack(float x0, float x1,
                                           uint32_t& hp, uint32_t& lp) {
    __nv_bfloat16 h0 = __float2bfloat16(x0);
    __nv_bfloat16 h1 = __float2bfloat16(x1);
    __nv_bfloat16 l0 = __float2bfloat16(x0 - __bfloat162float(h0));
    __nv_bfloat16 l1 = __float2bfloat16(x1 - __bfloat162float(h1));
    hp = ((uint32_t)__bfloat16_as_ushort(h1) << 16) | __bfloat16_as_ushort(h0);
    lp = ((uint32_t)__bfloat16_as_ushort(l1) << 16) | __bfloat16_as_ushort(l0);
}

// split fp32 -> bf16 hi/lo, 4 elems per thread
__global__ void split4_kernel(const float* __restrict__ in,
                              __nv_bfloat16* __restrict__ hi,
                              __nv_bfloat16* __restrict__ lo, int n4) {
    int i = blockIdx.x * blockDim.x + threadIdx.x;
    if (i >= n4) return;
    float4 v = ((const float4*)in)[i];
    uint32_t h0, l0, h1, l1;
    split2pack(v.x, v.y, h0, l0);
    split2pack(v.z, v.w, h1, l1);
    ((uint2*)hi)[i] = make_uint2(h0, h1);
    ((uint2*)lo)[i] = make_uint2(l0, l1);
}

// ------------------------- 3x-bf16 tensor GEMM (mma.m16n8k16) ---------------
// C[m,n] = sum_k A[m,k] * B[n,k] (+ bias), operands pre-split bf16 hi/lo.
// D = Ah*Bh + Al*Bh + Ah*Bl.  Block 128x128, BK=16, 256 thr, warp tile 64x32.
#define MMA_BF16(c, a0, a1, a2, a3, b0, b1)                                   \
    asm volatile(                                                             \
        "mma.sync.aligned.m16n8k16.row.col.f32.bf16.bf16.f32 "                \
        "{%0,%1,%2,%3}, {%4,%5,%6,%7}, {%8,%9}, {%0,%1,%2,%3};"               \
        : "+f"((c)[0]), "+f"((c)[1]), "+f"((c)[2]), "+f"((c)[3])              \
        : "r"(a0), "r"(a1), "r"(a2), "r"(a3), "r"(b0), "r"(b1))

__global__ __launch_bounds__(256) void bf16gemm3x_nt(
    const __nv_bfloat16* __restrict__ Ahi, const __nv_bfloat16* __restrict__ Alo,
    const __nv_bfloat16* __restrict__ Bhi, const __nv_bfloat16* __restrict__ Blo,
    const float* __restrict__ bias, float* __restrict__ C,
    int M, int N, int K, int Nw) {
    // smem: uint32 bf16-pairs, [stage][k-pair(8) = 16 k][m], pad 136
    __shared__ uint32_t Ah[2][8][136], Al[2][8][136];
    __shared__ uint32_t Bh[2][8][136], Bl[2][8][136];
    const int tid = threadIdx.x;
    const int bm = blockIdx.y * 128, bn = blockIdx.x * 128;
    const int lane = tid & 31, warp = tid >> 5;
    const int wm = (warp & 1) * 64, wn = (warp >> 1) * 32;
    const int lr = tid >> 1;          // 0..127 tile row
    const int lc8 = (tid & 1) * 8;    // k sub-block: 0 or 8
    const int kpb = lc8 >> 1;         // pair base: 0 or 4
    const __nv_bfloat16* pAh = Ahi + (size_t)(bm + lr) * K + lc8;
    const __nv_bfloat16* pAl = Alo + (size_t)(bm + lr) * K + lc8;
    const int bRow = bn + lr;
    const bool bOk = bRow < Nw;
    const __nv_bfloat16* pBh = Bhi + (size_t)(bOk ? bRow : 0) * K + lc8;
    const __nv_bfloat16* pBl = Blo + (size_t)(bOk ? bRow : 0) * K + lc8;

    float acc[4][4][4];
#pragma unroll
    for (int mt = 0; mt < 4; mt++)
#pragma unroll
        for (int nt = 0; nt < 4; nt++)
#pragma unroll
            for (int r = 0; r < 4; r++) acc[mt][nt][r] = 0.f;

    const uint4 z4 = make_uint4(0, 0, 0, 0);
    uint4 ah = *(const uint4*)pAh;          // 8 bf16 = 4 k-pairs
    uint4 al = *(const uint4*)pAl;
    uint4 bh = bOk ? *(const uint4*)pBh : z4;
    uint4 bl = bOk ? *(const uint4*)pBl : z4;
    int cur = 0;
    const int kq = lane & 3, gq = lane >> 2;

    for (int k0 = 0; k0 < K; k0 += 16) {
        Ah[cur][kpb + 0][lr] = ah.x; Ah[cur][kpb + 1][lr] = ah.y;
        Ah[cur][kpb + 2][lr] = ah.z; Ah[cur][kpb + 3][lr] = ah.w;
        Al[cur][kpb + 0][lr] = al.x; Al[cur][kpb + 1][lr] = al.y;
        Al[cur][kpb + 2][lr] = al.z; Al[cur][kpb + 3][lr] = al.w;
        Bh[cur][kpb + 0][lr] = bh.x; Bh[cur][kpb + 1][lr] = bh.y;
        Bh[cur][kpb + 2][lr] = bh.z; Bh[cur][kpb + 3][lr] = bh.w;
        Bl[cur][kpb + 0][lr] = bl.x; Bl[cur][kpb + 1][lr] = bl.y;
        Bl[cur][kpb + 2][lr] = bl.z; Bl[cur][kpb + 3][lr] = bl.w;
        if (k0 + 16 < K) {
            ah = *(const uint4*)(pAh + k0 + 16);
            al = *(const uint4*)(pAl + k0 + 16);
            bh = bOk ? *(const uint4*)(pBh + k0 + 16) : z4;
            bl = bOk ? *(const uint4*)(pBl + k0 + 16) : z4;
        }
        __syncthreads();

        uint32_t fbh[4][2], fbl[4][2];
#pragma unroll
        for (int nt = 0; nt < 4; nt++) {
            int nb = wn + nt * 8 + gq;
            fbh[nt][0] = Bh[cur][kq][nb];
            fbh[nt][1] = Bh[cur][kq + 4][nb];
            fbl[nt][0] = Bl[cur][kq][nb];
            fbl[nt][1] = Bl[cur][kq + 4][nb];
        }
#pragma unroll
        for (int mt = 0; mt < 4; mt++) {
            int mb = wm + mt * 16 + gq;
            uint32_t ah0 = Ah[cur][kq][mb];
            uint32_t ah1 = Ah[cur][kq][mb + 8];
            uint32_t ah2 = Ah[cur][kq + 4][mb];
            uint32_t ah3 = Ah[cur][kq + 4][mb + 8];
            uint32_t al0 = Al[cur][kq][mb];
            uint32_t al1 = Al[cur][kq][mb + 8];
            uint32_t al2 = Al[cur][kq + 4][mb];
            uint32_t al3 = Al[cur][kq + 4][mb + 8];
#pragma unroll
            for (int nt = 0; nt < 4; nt++) {
                MMA_BF16(acc[mt][nt], ah0, ah1, ah2, ah3, fbh[nt][0], fbh[nt][1]);
                MMA_BF16(acc[mt][nt], al0, al1, al2, al3, fbh[nt][0], fbh[nt][1]);
                MMA_BF16(acc[mt][nt], ah0, ah1, ah2, ah3, fbl[nt][0], fbl[nt][1]);
            }
        }
        cur ^= 1;
    }

#pragma unroll
    for (int mt = 0; mt < 4; mt++) {
#pragma unroll
        for (int nt = 0; nt < 4; nt++) {
            int row = bm + wm + mt * 16 + gq;
            int col = bn + wn + nt * 8 + kq * 2;
            if (col < N) {
                float b0 = bias ? bias[col] : 0.f;
                float b1 = bias ? bias[col + 1] : 0.f;
                C[(size_t)row * N + col] = acc[mt][nt][0] + b0;
                C[(size_t)row * N + col + 1] = acc[mt][nt][1] + b1;
                C[(size_t)(row + 8) * N + col] = acc[mt][nt][2] + b0;
                C[(size_t)(row + 8) * N + col + 1] = acc[mt][nt][3] + b1;
            }
        }
    }
}

// ------------------------- weight fold --------------------------------------
__global__ void fold_kernel(const float* __restrict__ inwA,
                            const float* __restrict__ projw,
                            float* __restrict__ W) {
    __shared__ float As[16][16];
    __shared__ float Bs[16][17];
    int tx = threadIdx.x, ty = threadIdx.y;
    int m = blockIdx.y * 16 + ty;
    int n = blockIdx.x * 16 + tx;
    float acc = 0.f;
    for (int k0 = 0; k0 < DM; k0 += 16) {
        As[ty][tx] = inwA[(size_t)m * DM + k0 + tx];
        Bs[ty][tx] = projw[(size_t)(k0 + ty) * DM + n];
        __syncthreads();
#pragma unroll
        for (int k = 0; k < 16; k++) acc += As[ty][k] * Bs[k][tx];
        __syncthreads();
    }
    W[(size_t)m * DM + n] = acc;
}

__global__ void foldc_kernel(const float* __restrict__ inwA,
                             const float* __restrict__ projb,
                             float* __restrict__ c) {
    int m = blockIdx.x * blockDim.x + threadIdx.x;
    if (m >= DI) return;
    float s = 0.f;
    for (int k = 0; k < DM; k++) s += inwA[(size_t)m * DM + k] * projb[k];
    c[m] = s;
}

// ------------------------- causal depthwise conv (4 taps) + silu ------------
// also emits bf16 hi/lo split of xc for the xproj GEMM
__global__ void conv_silu_kernel(const float* __restrict__ xa,
                                 const float* __restrict__ convw,
                                 const float* __restrict__ convb,
                                 float* __restrict__ xc,
                                 __nv_bfloat16* __restrict__ xchi,
                                 __nv_bfloat16* __restrict__ xclo) {
    size_t i = (size_t)blockIdx.x * blockDim.x + threadIdx.x;
    int d4 = (int)(i & 255);
    size_t bt = i >> 8;
    int t = (int)(bt & (LQ - 1));
    const float4* xa4 = (const float4*)xa;
    const float4* w4 = (const float4*)convw;
    float4 w0 = w4[d4 * 4 + 0], w1 = w4[d4 * 4 + 1];
    float4 w2 = w4[d4 * 4 + 2], w3 = w4[d4 * 4 + 3];
    float4 bias = ((const float4*)convb)[d4];
    float4 z4 = make_float4(0.f, 0.f, 0.f, 0.f);
    float4 xv3 = xa4[bt * 256 + d4];
    float4 xv2 = (t >= 1) ? xa4[(bt - 1) * 256 + d4] : z4;
    float4 xv1 = (t >= 2) ? xa4[(bt - 2) * 256 + d4] : z4;
    float4 xv0 = (t >= 3) ? xa4[(bt - 3) * 256 + d4] : z4;
    float o0 = w0.x * xv0.x + w0.y * xv1.x + w0.z * xv2.x + w0.w * xv3.x + bias.x;
    float o1 = w1.x * xv0.y + w1.y * xv1.y + w1.z * xv2.y + w1.w * xv3.y + bias.y;
    float o2 = w2.x * xv0.z + w2.y * xv1.z + w2.z * xv2.z + w2.w * xv3.z + bias.z;
    float o3 = w3.x * xv0.w + w3.y * xv1.w + w3.z * xv2.w + w3.w * xv3.w + bias.w;
    float4 out = make_float4(silu_f(o0), silu_f(o1), silu_f(o2), silu_f(o3));
    ((float4*)xc)[bt * 256 + d4] = out;
    uint32_t h0, l0, h1, l1;
    split2pack(out.x, out.y, h0, l0);
    split2pack(out.z, out.w, h1, l1);
    ((uint2*)xchi)[bt * 256 + d4] = make_uint2(h0, h1);
    ((uint2*)xclo)[bt * 256 + d4] = make_uint2(l0, l1);
}

// ------------------------- chunked selective scan, phase 1 ------------------
__global__ __launch_bounds__(128) void scan_chunk_kernel(
    const float* __restrict__ xc, const float* __restrict__ xdb,
    const float* __restrict__ dtw, const float* __restrict__ dtb,
    const float* __restrict__ Alog,
    float* __restrict__ hpart, float* __restrict__ sumdt) {
    const int d = blockIdx.x * 128 + threadIdx.x;
    const int c = blockIdx.y, b = blockIdx.z;
    float w[DTR];
#pragma unroll
    for (int r = 0; r < DTR; r++) w[r] = dtw[(size_t)d * DTR + r];
    const float bias = dtb[d];
    float a[NS];
    bool fast = true;
#pragma unroll
    for (int n = 0; n < NS; n++) {
        a[n] = -__expf(Alog[(size_t)d * NS + n]);
        fast = fast && (fabsf(a[n] + (float)(n + 1)) < 1e-4f * (float)(n + 1));
    }
    float h[NS];
#pragma unroll
    for (int n = 0; n < NS; n++) h[n] = 0.f;
    float sdt = 0.f;

    __shared__ float sB[32][48];
    const int t_base = c * CHUNK;
    for (int t0 = 0; t0 < CHUNK; t0 += 32) {
        __syncthreads();
        for (int i = threadIdx.x; i < 384; i += 128) {
            int tt = i / 12, j4 = i % 12;
            float4 v = *(const float4*)(xdb +
                ((size_t)b * LQ + t_base + t0 + tt) * 64 + j4 * 4);
            *(float4*)&sB[tt][j4 * 4] = v;
        }
        __syncthreads();
#pragma unroll 4
        for (int tt = 0; tt < 32; tt++) {
            const float* row = sB[tt];
            float v = bias;
#pragma unroll
            for (int r = 0; r < DTR; r++) v += row[r] * w[r];
            const size_t t = (size_t)(t_base + t0 + tt);
            float u = xc[((size_t)b * LQ + t) * DI + d];
            float ev = __expf(v);
            float dt = (v > 15.f) ? v : log1pf(ev);
            sdt += dt;
            float coef = dt * u;
            if (fast) {
                float e = (v > 15.f) ? __expf(-v) : 1.f / (1.f + ev);
                float p = e;
#pragma unroll
                for (int n = 0; n < NS; n++) {
                    h[n] = h[n] * p + coef * row[32 + n];
                    p *= e;
                }
            } else {
#pragma unroll
                for (int n = 0; n < NS; n++)
                    h[n] = h[n] * __expf(dt * a[n]) + coef * row[32 + n];
            }
        }
    }
    sumdt[((size_t)b * NCHUNK + c) * DI + d] = sdt;
#pragma unroll
    for (int n = 0; n < NS; n++)
        hpart[(((size_t)b * NCHUNK + c) * NS + n) * DI + d] = h[n];
}

// ------------------------- scan phase 2 -------------------------------------
__global__ void scan_combine_kernel(const float* __restrict__ hpart,
                                    const float* __restrict__ sumdt,
                                    const float* __restrict__ Alog,
                                    float* __restrict__ hfin) {
    int i = blockIdx.x * blockDim.x + threadIdx.x;
    int d = i & (DI - 1);
    int b = i / DI;
    float a[NS];
    bool fast = true;
#pragma unroll
    for (int n = 0; n < NS; n++) {
        a[n] = -__expf(Alog[(size_t)d * NS + n]);
        fast = fast && (fabsf(a[n] + (float)(n + 1)) < 1e-4f * (float)(n + 1));
    }
    float H[NS];
#pragma unroll
    for (int n = 0; n < NS; n++) H[n] = 0.f;
    for (int c = 0; c < NCHUNK; c++) {
        float s = sumdt[((size_t)b * NCHUNK + c) * DI + d];
        const float* hp = hpart + (((size_t)b * NCHUNK + c) * NS) * DI + d;
        if (fast) {
            float e = __expf(-s), p = e;
#pragma unroll
            for (int n = 0; n < NS; n++) {
                H[n] = H[n] * p + hp[(size_t)n * DI];
                p *= e;
            }
        } else {
#pragma unroll
            for (int n = 0; n < NS; n++)
                H[n] = H[n] * __expf(a[n] * s) + hp[(size_t)n * DI];
        }
    }
#pragma unroll
    for (int n = 0; n < NS; n++) hfin[((size_t)b * NS + n) * DI + d] = H[n];
}

// ------------------------- finale (last-token only) -------------------------
__global__ void xplast_kernel(const float* __restrict__ x,
                              const float* __restrict__ projw,
                              const float* __restrict__ projb,
                              float* __restrict__ xpl) {
    int b = blockIdx.x, m = threadIdx.x;
    __shared__ float xs[DM];
    xs[m] = x[((size_t)b * LQ + (LQ - 1)) * DM + m];
    __syncthreads();
    float s = projb[m];
    const float* wr = projw + (size_t)m * DM;
    for (int k = 0; k < DM; k++) s += xs[k] * wr[k];
    xpl[b * DM + m] = s;
}

__global__ void f2_kernel(const float* __restrict__ xpl,
                          const float* __restrict__ inwf,
                          const float* __restrict__ inwb,
                          float* __restrict__ zf, float* __restrict__ zb,
                          float* __restrict__ xab0) {
    int b = blockIdx.y, kind = blockIdx.x, d = threadIdx.x;
    __shared__ float xs[DM];
    if (d < DM) xs[d] = xpl[b * DM + d];
    __syncthreads();
    const float* wrow;
    if (kind == 0) wrow = inwf + (size_t)(DI + d) * DM;
    else if (kind == 1) wrow = inwb + (size_t)(DI + d) * DM;
    else wrow = inwb + (size_t)d * DM;
    float s = 0.f;
    for (int k = 0; k < DM; k++) s += xs[k] * wrow[k];
    if (kind == 0) zf[b * DI + d] = s;
    else if (kind == 1) zb[b * DI + d] = s;
    else xab0[b * DI + d] = s;
}

__global__ void f3a_kernel(const float* __restrict__ xab0,
                           const float* __restrict__ convwb,
                           const float* __restrict__ convbb,
                           float* __restrict__ xcb0) {
    int i = blockIdx.x * blockDim.x + threadIdx.x;
    int d = i & (DI - 1);
    float t = convwb[d * 4 + 3] * xab0[i] + convbb[d];
    xcb0[i] = silu_f(t);
}

__global__ void f3b_kernel(const float* __restrict__ xcb0,
                           const float* __restrict__ xprojwb,
                           float* __restrict__ xdbb) {
    int b = blockIdx.x, j = threadIdx.x;
    __shared__ float xs[DI];
    for (int k = threadIdx.x; k < DI; k += 64) xs[k] = xcb0[b * DI + k];
    __syncthreads();
    float s = 0.f;
    const float* wr = xprojwb + (size_t)j * DI;
    for (int k = 0; k < DI; k++) s += xs[k] * wr[k];
    xdbb[b * 64 + j] = s;
}

__global__ void f3c_kernel(const float* __restrict__ xdbb,
                           const float* __restrict__ dtwb,
                           const float* __restrict__ dtbb,
                           const float* __restrict__ Db,
                           const float* __restrict__ xcb0,
                           const float* __restrict__ hfin,
                           const float* __restrict__ xdb,
                           const float* __restrict__ xc,
                           const float* __restrict__ Df,
                           const float* __restrict__ zf,
                           const float* __restrict__ zb,
                           float* __restrict__ gf, float* __restrict__ gb) {
    int i = blockIdx.x * blockDim.x + threadIdx.x;
    int d = i & (DI - 1);
    int b = i / DI;
    const float* xb = xdbb + b * 64;
    float v = dtbb[d];
#pragma unroll
    for (int r = 0; r < DTR; r++) v += xb[r] * dtwb[(size_t)d * DTR + r];
    float ev = __expf(v);
    float dt = (v > 15.f) ? v : log1pf(ev);
    float S = 0.f;
#pragma unroll
    for (int n = 0; n < NS; n++) S += xb[32 + n] * xb[48 + n];
    float u = xcb0[i];
    float yb = dt * u * S + u * Db[d];
    gb[i] = yb * silu_f(zb[i]);
    const float* Crow = xdb + ((size_t)b * LQ + LQ - 1) * 64 + 48;
    float yf = 0.f;
#pragma unroll
    for (int n = 0; n < NS; n++)
        yf += hfin[((size_t)b * NS + n) * DI + d] * Crow[n];
    yf += xc[((size_t)b * LQ + LQ - 1) * DI + d] * Df[d];
    gf[i] = yf * silu_f(zf[i]);
}

__global__ void f4_kernel(const float* __restrict__ gf,
                          const float* __restrict__ gb,
                          const float* __restrict__ outwf,
                          const float* __restrict__ outwb,
                          float* __restrict__ outf, float* __restrict__ outb) {
    int side = blockIdx.x, b = blockIdx.y;
    int m = threadIdx.x;
    __shared__ float gs[DI];
    const float* g = side ? gb : gf;
    for (int k = m; k < DI; k += DM) gs[k] = g[b * DI + k];
    __syncthreads();
    const float* wr = (side ? outwb : outwf) + (size_t)m * DI;
    float s = 0.f;
    for (int k = 0; k < DI; k++) s += gs[k] * wr[k];
    (side ? outb : outf)[b * DM + m] = s;
}

__global__ void f5_kernel(const float* __restrict__ outf,
                          const float* __restrict__ outb,
                          const float* __restrict__ fw,
                          const float* __restrict__ fb,
                          const float* __restrict__ lng,
                          const float* __restrict__ lnb,
                          float* __restrict__ out) {
    int b = blockIdx.x, m = threadIdx.x;
    __shared__ float cat[2 * DM];
    __shared__ float red[DM];
    cat[m] = outf[b * DM + m];
    cat[DM + m] = outb[b * DM + m];
    __syncthreads();
    float r = fb[m];
    const float* wr = fw + (size_t)m * 2 * DM;
    for (int j = 0; j < 2 * DM; j++) r += cat[j] * wr[j];
    red[m] = r;
    __syncthreads();
    for (int s = 256; s > 0; s >>= 1) {
        if (m < s) red[m] += red[m + s];
        __syncthreads();
    }
    float mu = red[0] * (1.f / DM);
    __syncthreads();
    float dv = r - mu;
    red[m] = dv * dv;
    __syncthreads();
    for (int s = 256; s > 0; s >>= 1) {
        if (m < s) red[m] += red[m + s];
        __syncthreads();
    }
    float var = red[0] * (1.f / DM);
    out[b * DM + m] = dv * rsqrtf(var + 1e-5f) * lng[m] + lnb[m];
}

// ------------------------- launch ------------------------------------------
extern "C" void kernel_launch(void* const* d_in, const int* in_sizes, int n_in,
                              void* d_out, int out_size) {
    (void)in_sizes; (void)n_in; (void)out_size;
    const float* x        = (const float*)d_in[0];
    const float* proj_w   = (const float*)d_in[1];
    const float* proj_b   = (const float*)d_in[2];
    const float* in_w_f   = (const float*)d_in[3];
    const float* conv_w_f = (const float*)d_in[4];
    const float* conv_b_f = (const float*)d_in[5];
    const float* xproj_w_f= (const float*)d_in[6];
    const float* dt_w_f   = (const float*)d_in[7];
    const float* dt_b_f   = (const float*)d_in[8];
    const float* A_log_f  = (const float*)d_in[9];
    const float* D_f      = (const float*)d_in[10];
    const float* out_w_f  = (const float*)d_in[11];
    const float* in_w_b   = (const float*)d_in[12];
    const float* conv_w_b = (const float*)d_in[13];
    const float* conv_b_b = (const float*)d_in[14];
    const float* xproj_w_b= (const float*)d_in[15];
    const float* dt_w_b   = (const float*)d_in[16];
    const float* dt_b_b   = (const float*)d_in[17];
    const float* A_log_b  = (const float*)d_in[18];
    const float* D_b      = (const float*)d_in[19];
    const float* out_w_b  = (const float*)d_in[20];
    const float* fusion_w = (const float*)d_in[21];
    const float* fusion_b = (const float*)d_in[22];
    const float* ln_g     = (const float*)d_in[23];
    const float* ln_b     = (const float*)d_in[24];
    float* out = (float*)d_out;

    float *W, *c, *xa, *xc, *xdb, *hpart, *sumdt, *hfin, *xpl;
    float *zf, *zb, *xab0, *xcb0, *xdbb, *gf, *gb, *outf, *outb;
    __nv_bfloat16 *xhi, *xlo, *Whi, *Wlo, *xchi, *xclo, *xpwhi, *xpwlo;
    cudaGetSymbolAddress((void**)&W, g_W);
    cudaGetSymbolAddress((void**)&c, g_c);
    cudaGetSymbolAddress((void**)&xa, g_xa);
    cudaGetSymbolAddress((void**)&xc, g_xc);
    cudaGetSymbolAddress((void**)&xdb, g_xdb);
    cudaGetSymbolAddress((void**)&hpart, g_hpart);
    cudaGetSymbolAddress((void**)&sumdt, g_sumdt);
    cudaGetSymbolAddress((void**)&hfin, g_hfin);
    cudaGetSymbolAddress((void**)&xpl, g_xplast);
    cudaGetSymbolAddress((void**)&zf, g_zf);
    cudaGetSymbolAddress((void**)&zb, g_zb);
    cudaGetSymbolAddress((void**)&xab0, g_xab0);
    cudaGetSymbolAddress((void**)&xcb0, g_xcb0);
    cudaGetSymbolAddress((void**)&xdbb, g_xdbb);
    cudaGetSymbolAddress((void**)&gf, g_gf);
    cudaGetSymbolAddress((void**)&gb, g_gb);
    cudaGetSymbolAddress((void**)&outf, g_outf);
    cudaGetSymbolAddress((void**)&outb, g_outb);
    cudaGetSymbolAddress((void**)&xhi, g_xhi);
    cudaGetSymbolAddress((void**)&xlo, g_xlo);
    cudaGetSymbolAddress((void**)&Whi, g_Whi);
    cudaGetSymbolAddress((void**)&Wlo, g_Wlo);
    cudaGetSymbolAddress((void**)&xchi, g_xchi);
    cudaGetSymbolAddress((void**)&xclo, g_xclo);
    cudaGetSymbolAddress((void**)&xpwhi, g_xpwhi);
    cudaGetSymbolAddress((void**)&xpwlo, g_xpwlo);

    const int M = BQ * LQ; // 32768

    // 1. fold weights + pre-split operands
    fold_kernel<<<dim3(DM / 16, DI / 16), dim3(16, 16)>>>(in_w_f, proj_w, W);
    foldc_kernel<<<DI / 256, 256>>>(in_w_f, proj_b, c);
    split4_kernel<<<(DI * DM / 4) / 256, 256>>>(W, Whi, Wlo, DI * DM / 4);
    split4_kernel<<<(M * DM / 4) / 256, 256>>>(x, xhi, xlo, M * DM / 4);
    split4_kernel<<<(64 * DI / 4) / 256, 256>>>(xproj_w_f, xpwhi, xpwlo,
                                                64 * DI / 4);
    // 2. xa = x @ W^T + c   (3x-bf16 mma, pre-split operands)
    bf16gemm3x_nt<<<dim3(DI / 128, M / 128), 256>>>(xhi, xlo, Whi, Wlo, c, xa,
                                                    M, DI, DM, DI);
    // 3. conv + silu (emits xc split)
    conv_silu_kernel<<<(M * (DI / 4)) / 256, 256>>>(xa, conv_w_f, conv_b_f,
                                                    xc, xchi, xclo);
    // 4. xproj (3x-bf16, N=64)
    bf16gemm3x_nt<<<dim3(1, M / 128), 256>>>(xchi, xclo, xpwhi, xpwlo, nullptr,
                                             xdb, M, 64, DI, 64);
    // 5. scan
    scan_chunk_kernel<<<dim3(DI / 128, NCHUNK, BQ), 128>>>(
        xc, xdb, dt_w_f, dt_b_f, A_log_f, hpart, sumdt);
    scan_combine_kernel<<<(BQ * DI) / 128, 128>>>(hpart, sumdt, A_log_f, hfin);
    // 6. finale (last-token only)
    xplast_kernel<<<BQ, DM>>>(x, proj_w, proj_b, xpl);
    f2_kernel<<<dim3(3, BQ), DI>>>(xpl, in_w_f, in_w_b, zf, zb, xab0);
    f3a_kernel<<<(BQ * DI) / 256, 256>>>(xab0, conv_w_b, conv_b_b, xcb0);
    f3b_kernel<<<BQ, 64>>>(xcb0, xproj_w_b, xdbb);
    f3c_kernel<<<(BQ * DI) / 256, 256>>>(xdbb, dt_w_b, dt_b_b, D_b, xcb0,
                                          hfin, xdb, xc, D_f, zf, zb, gf, gb);
    f4_kernel<<<dim3(2, BQ), DM>>>(gf, gb, out_w_f, out_w_b, outf, outb);
    f5_kernel<<<BQ, DM>>>(outf, outb, fusion_w, fusion_b, ln_g, ln_b, out);
}